// round 15
// baseline (speedup 1.0000x reference)
#include <cuda_runtime.h>
#include <cuda_bf16.h>

#define T_MAX   16384
#define WIDTH   1024
#define GRIDP   32          // CTAs per layer group
#define NGROUP  3
#define GRID    (GRIDP * NGROUP)   // 96
#define THREADS 512
#define NW      16
#define CHUNK   32          // output dims per CTA (1024/32)
#define WS      16
#define ALPHA   21
#define POLL_BUDGET (1u << 17)

typedef unsigned long long u64;

// ---- global scratch (static __device__ arrays: allocation-free) ----
// Pair format: high 32 bits = epoch, low 32 bits = f32 value bits.
__device__ __align__(16) int g_flags0[GRID];        // precompute barrier
__device__ int g_abort;
__device__ __align__(16) u64 g_h1p[WIDTH];          // h1 pairs (written by group 0)
__device__ __align__(16) u64 g_h2p[WIDTH];          // h2 pairs (written by group 1)
__device__ __align__(16) u64 g_pp[2 * GRIDP];       // partial pairs, parity-slotted (group 2)
__device__ float g_hpre[(size_t)T_MAX * WIDTH];     // one-hot part of layer0, per timestep

__global__ void init_kernel() {
    int i = blockIdx.x * blockDim.x + threadIdx.x;
    if (i < WIDTH)     { g_h1p[i] = 0ull; g_h2p[i] = 0ull; }
    if (i < 2 * GRIDP) g_pp[i] = 0ull;
    if (i < GRID)      g_flags0[i] = 0;
    if (i == 0)        g_abort = 0;
}

// ------------------------------- helpers ----------------------------------
__device__ __forceinline__ void st_pair(u64* p, float v, unsigned e) {
    u64 x = ((u64)e << 32) | (u64)__float_as_uint(v);
    asm volatile("st.relaxed.gpu.global.u64 [%0], %1;" :: "l"(p), "l"(x) : "memory");
}
__device__ __forceinline__ int ld_abort() {
    int a;
    asm volatile("ld.global.cg.u32 %0, [%1];" : "=r"(a) : "l"(&g_abort) : "memory");
    return a;
}
__device__ __forceinline__ void set_abort() {
    asm volatile("st.global.cg.u32 [%0], %1;" :: "l"(&g_abort), "r"(1) : "memory");
}

// Per-thread: poll 2 consecutive pairs (one 16B load) until both epochs >= need.
// Burst-then-sleep: 2 hard polls catch near-landings, then nanosleep(60) keeps
// L2 pressure in the known-safe band (hard spin proven fatal in R14).
__device__ __forceinline__ float2 poll2(const u64* base, unsigned need, int& dead) {
    if (dead) return make_float2(0.f, 0.f);
    unsigned cnt = 0;
    for (;;) {
        u64 a, b;
        asm volatile("ld.global.cg.v2.u64 {%0,%1}, [%2];"
                     : "=l"(a), "=l"(b) : "l"(base) : "memory");
        if ((unsigned)(a >> 32) >= need && (unsigned)(b >> 32) >= need)
            return make_float2(__uint_as_float((unsigned)a), __uint_as_float((unsigned)b));
        ++cnt;
        if ((cnt & 63u) == 0u) {
            if (ld_abort()) { dead = 1; break; }
            if (cnt > POLL_BUDGET) { set_abort(); dead = 1; break; }
        }
        if (cnt > 2) __nanosleep(60);
    }
    return make_float2(0.f, 0.f);
}

// Bounded flag wait for the one-time precompute barrier (96 flags = 24 int4).
__device__ __forceinline__ void flagwait0(int lane) {
    int idx = (lane < 24) ? lane : (lane - 24);
    const int4* fp = reinterpret_cast<const int4*>(g_flags0) + idx;
    unsigned cnt = 0;
    for (;;) {
        int4 v; int ab;
        asm volatile("ld.global.cg.v4.u32 {%0,%1,%2,%3}, [%4];"
                     : "=r"(v.x), "=r"(v.y), "=r"(v.z), "=r"(v.w)
                     : "l"(fp) : "memory");
        asm volatile("ld.global.cg.u32 %0, [%1];"
                     : "=r"(ab) : "l"(&g_abort) : "memory");
        bool done = (v.x >= 1 && v.y >= 1 && v.z >= 1 && v.w >= 1) || (ab != 0);
        if (__all_sync(0xffffffffu, done)) break;
        if (++cnt > POLL_BUDGET) {
            if (lane == 0) set_abort();
            break;
        }
        __nanosleep(150);
    }
    __threadfence();
}

// One warp computes one dot(w_row[1024], h[1024]) from shared memory. (R12 verbatim)
__device__ __forceinline__ float gemv_warp(const float* __restrict__ wrow,
                                           const float* __restrict__ hbuf, int lane) {
    const float4* w4 = reinterpret_cast<const float4*>(wrow);
    const float4* h4 = reinterpret_cast<const float4*>(hbuf);
    float acc = 0.0f;
    #pragma unroll
    for (int i = 0; i < 8; i++) {
        float4 a = w4[i * 32 + lane];
        float4 b = h4[i * 32 + lane];
        acc += a.x * b.x + a.y * b.y + a.z * b.z + a.w * b.w;
    }
    #pragma unroll
    for (int d = 16; d > 0; d >>= 1) acc += __shfl_xor_sync(0xffffffffu, acc, d);
    return acc;
}

__global__ void __launch_bounds__(THREADS, 1)
seqff_kernel(const int* __restrict__ x,
             const float* __restrict__ W0,
             const float* __restrict__ b0,
             const float* __restrict__ Wh,
             const float* __restrict__ bh,
             const float* __restrict__ Wo,
             const float* __restrict__ bo,
             float* __restrict__ out,
             int T)
{
    extern __shared__ float smem[];
    float* Whs   = smem;                       // [32][1024] ONE layer's rows (128KB)
    float* hbuf  = Whs + CHUNK * WIDTH;        // 1024: staged input vector / h0
    float* ring  = hbuf + WIDTH;               // 16: y history window (group 0 only)
    float* wos   = ring + 16;                  // 32 (group 2 only)
    float* out32 = wos + 32;                   // 32: per-layer chunk outputs

    const int tid   = threadIdx.x;
    const int lane  = tid & 31;
    const int w     = tid >> 5;
    const int bid   = blockIdx.x;
    const int group = bid / GRIDP;             // 0: h0+L1, 1: L2, 2: L3+partial
    const int gid   = bid - group * GRIDP;
    const int o0    = gid * CHUNK;

    // ===================== load weights (once) =====================
    float2 wys[WS];
    #pragma unroll
    for (int k = 0; k < WS; k++)
        wys[k] = *reinterpret_cast<const float2*>(W0 + (size_t)(357 + k) * WIDTH + 2 * tid);

    for (int idx = tid; idx < CHUNK * WIDTH; idx += THREADS) {
        int r = idx >> 10, j = idx & (WIDTH - 1);
        Whs[idx] = Wh[(size_t)group * WIDTH * WIDTH + (size_t)j * WIDTH + o0 + r];
    }
    if (tid < CHUNK) wos[tid] = Wo[o0 + tid];
    if (tid < 16)    ring[tid] = -10.0f;
    const float bo_reg = __ldg(bo);
    const float bhA = __ldg(bh + (size_t)group * WIDTH + o0 + w);
    const float bhB = __ldg(bh + (size_t)group * WIDTH + o0 + w + 16);
    __syncthreads();

    // =============== precompute one-hot part of layer 0 for all t ===============
    for (int t = bid; t < T; t += GRID) {
        float2 acc = *reinterpret_cast<const float2*>(b0 + 2 * tid);
        if (t >= WS) {
            #pragma unroll
            for (int p = 0; p < WS + 1; p++) {
                int r = p * ALPHA + __ldg(x + t - WS + p);
                float2 wv = *reinterpret_cast<const float2*>(W0 + (size_t)r * WIDTH + 2 * tid);
                acc.x += wv.x; acc.y += wv.y;
            }
        } else {
            for (int p = 0; p < WS + 1; p++) {
                int pos = t - WS + p;
                if (pos >= 0) {
                    int r = p * ALPHA + __ldg(x + pos);
                    float2 wv = *reinterpret_cast<const float2*>(W0 + (size_t)r * WIDTH + 2 * tid);
                    acc.x += wv.x; acc.y += wv.y;
                } else {
                    for (int a = 0; a < ALPHA; a++) {
                        int r = p * ALPHA + a;
                        float2 wv = *reinterpret_cast<const float2*>(W0 + (size_t)r * WIDTH + 2 * tid);
                        acc.x += wv.x; acc.y += wv.y;
                    }
                }
            }
        }
        *reinterpret_cast<float2*>(g_hpre + (size_t)t * WIDTH + 2 * tid) = acc;
    }
    __syncthreads();
    if (tid == 0) {
        __threadfence();
        asm volatile("st.global.cg.u32 [%0], %1;" :: "l"(g_flags0 + bid), "r"(1) : "memory");
    }
    if (w == 0) flagwait0(lane);
    __syncthreads();

    int dead = 0;

    // Group 0: h0_partial for step 0 (window y's all -10 except last, which is
    // y_{-1} = -10 too, but we fold only 15 terms here; term 15 added on "arrival").
    float2 h0p_reg = make_float2(0.f, 0.f);
    float2 hpre_next = make_float2(0.f, 0.f);
    if (group == 0) {
        float2 acc = *reinterpret_cast<const float2*>(g_hpre + 2 * tid);
        #pragma unroll
        for (int k = 0; k < 15; k++) {
            acc.x += -10.0f * wys[k].x;
            acc.y += -10.0f * wys[k].y;
        }
        h0p_reg = acc;
        if (T > 1)
            hpre_next = *reinterpret_cast<const float2*>(g_hpre + (size_t)WIDTH + 2 * tid);
    }

    // ============================ sequential main loop ============================
    for (int t = 0; t < T; t++) {
        if (group == 0) {
            // ---- y_{t-1} from 32 partial pairs (every warp, redundantly) ----
            float y = -10.0f;
            if (t > 0) {
                float2 pv = poll2(g_pp + ((t - 1) & 1) * GRIDP + 2 * (lane & 15), (unsigned)t, dead);
                float s = (lane < 16) ? (pv.x + pv.y) : 0.0f;
                #pragma unroll
                for (int d = 16; d > 0; d >>= 1) s += __shfl_xor_sync(0xffffffffu, s, d);
                y = fmaxf(s + bo_reg, 0.0f);
                if (bid == 0 && tid == 0) out[t - 1] = y;
                if (lane == 0) ring[(t + 15) & 15] = y;
                __syncwarp();
            }
            // finalize h0: precomputed partial + last window term
            {
                float2 h = h0p_reg;
                h.x = fmaxf(h.x + y * wys[15].x, 0.0f);
                h.y = fmaxf(h.y + y * wys[15].y, 0.0f);
                *reinterpret_cast<float2*>(hbuf + 2 * tid) = h;
            }
            __syncthreads();
            // layer-1 GEMV (2 rows/warp), coalesced publish h1 pairs
            {
                float v0 = gemv_warp(Whs + w * WIDTH, hbuf, lane);
                float v1 = gemv_warp(Whs + (w + 16) * WIDTH, hbuf, lane);
                if (lane == 0) {
                    out32[w]      = fmaxf(v0 + bhA, 0.0f);
                    out32[w + 16] = fmaxf(v1 + bhB, 0.0f);
                }
            }
            __syncthreads();
            if (tid < CHUNK)
                st_pair(&g_h1p[o0 + tid], out32[tid], (unsigned)(t + 1));
            // ---- idle window: h0_partial for step t+1 (15 known ring terms) ----
            {
                float2 acc = hpre_next;
                #pragma unroll
                for (int k = 0; k < 15; k++) {
                    float yk = ring[(t + 1 + k) & 15];
                    acc.x += yk * wys[k].x;
                    acc.y += yk * wys[k].y;
                }
                h0p_reg = acc;
                if (t + 2 < T)
                    hpre_next = *reinterpret_cast<const float2*>(g_hpre + (size_t)(t + 2) * WIDTH + 2 * tid);
            }
        } else if (group == 1) {
            // ---- poll full h1 (this thread's 2 dims), GEMV layer 2, publish h2 ----
            {
                float2 hv = poll2(g_h1p + 2 * tid, (unsigned)(t + 1), dead);
                *reinterpret_cast<float2*>(hbuf + 2 * tid) = hv;
            }
            __syncthreads();                   // bar1: hbuf staged
            {
                float v0 = gemv_warp(Whs + w * WIDTH, hbuf, lane);
                float v1 = gemv_warp(Whs + (w + 16) * WIDTH, hbuf, lane);
                if (lane == 0) {
                    out32[w]      = fmaxf(v0 + bhA, 0.0f);
                    out32[w + 16] = fmaxf(v1 + bhB, 0.0f);
                }
            }
            __syncthreads();                   // bar2: all hbuf reads + out32 writes done
            if (tid < CHUNK)
                st_pair(&g_h2p[o0 + tid], out32[tid], (unsigned)(t + 1));
            // no bar3: bar2 orders hbuf reads before next iter's poll writes;
            // publisher reads out32 before its own next poll/bar1.
        } else {
            // ---- poll full h2, GEMV layer 3, fold Wo dot, publish partial ----
            {
                float2 hv = poll2(g_h2p + 2 * tid, (unsigned)(t + 1), dead);
                *reinterpret_cast<float2*>(hbuf + 2 * tid) = hv;
            }
            __syncthreads();                   // bar1
            {
                float v0 = gemv_warp(Whs + w * WIDTH, hbuf, lane);
                float v1 = gemv_warp(Whs + (w + 16) * WIDTH, hbuf, lane);
                if (lane == 0) {
                    out32[w]      = fmaxf(v0 + bhA, 0.0f);
                    out32[w + 16] = fmaxf(v1 + bhB, 0.0f);
                }
            }
            __syncthreads();                   // bar2
            if (tid == 0) {
                float p = 0.0f;
                #pragma unroll
                for (int i = 0; i < CHUNK; i++) p += out32[i] * wos[i];
                st_pair(&g_pp[(t & 1) * GRIDP + gid], p, (unsigned)(t + 1));
            }
            // no bar3 (same audit as group 1; tid0 reads out32 after bar2,
            // writers only touch out32 after next bar1 which tid0 must reach)
        }
    }

    // ---------------- epilogue: final output y[T-1] ----------------
    if (bid == 0 && w == 0) {
        float2 pv = poll2(g_pp + ((T - 1) & 1) * GRIDP + 2 * (lane & 15), (unsigned)T, dead);
        float s = (lane < 16) ? (pv.x + pv.y) : 0.0f;
        #pragma unroll
        for (int d = 16; d > 0; d >>= 1) s += __shfl_xor_sync(0xffffffffu, s, d);
        if (lane == 0) out[T - 1] = fmaxf(s + bo_reg, 0.0f);
    }
}

extern "C" void kernel_launch(void* const* d_in, const int* in_sizes, int n_in,
                              void* d_out, int out_size)
{
    const int*   x  = (const int*)  d_in[0];
    const float* W0 = (const float*)d_in[1];
    const float* b0 = (const float*)d_in[2];
    const float* Wh = (const float*)d_in[3];
    const float* bh = (const float*)d_in[4];
    const float* Wo = (const float*)d_in[5];
    const float* bo = (const float*)d_in[6];
    float* out = (float*)d_out;
    int T = in_sizes[0];
    if (T > T_MAX) T = T_MAX;

    const int smem_bytes = (CHUNK * WIDTH + WIDTH + 16 + 32 + 32) * 4;  // ~136KB
    cudaFuncSetAttribute(seqff_kernel, cudaFuncAttributeMaxDynamicSharedMemorySize, smem_bytes);

    init_kernel<<<4, 512>>>();
    seqff_kernel<<<GRID, THREADS, smem_bytes>>>(x, W0, b0, Wh, bh, Wo, bo, out, T);
}

// round 16
// speedup vs baseline: 1.4296x; 1.4296x over previous
#include <cuda_runtime.h>
#include <cuda_bf16.h>

#define T_MAX   16384
#define WIDTH   1024
#define GRIDP   32          // CTAs per layer group
#define NGROUP  3
#define GRID    (GRIDP * NGROUP)   // 96
#define THREADS 512
#define NW      16
#define CHUNK   32          // output dims per CTA (1024/32)
#define WS      16
#define ALPHA   21
#define PPAD    16          // u64 stride per partial slot -> one 128B line each
#define POLL_BUDGET (1u << 17)

typedef unsigned long long u64;

// ---- global scratch (static __device__ arrays: allocation-free) ----
// Pair format: high 32 bits = epoch, low 32 bits = f32 value bits.
__device__ __align__(16) int g_flags0[GRID];        // precompute barrier
__device__ int g_abort;
__device__ __align__(16) u64 g_h1p[WIDTH];          // h1 pairs (written by group 0)
__device__ __align__(16) u64 g_h2p[WIDTH];          // h2 pairs (written by group 1)
__device__ __align__(16) u64 g_pp[2 * GRIDP * PPAD]; // padded partial pairs, parity-slotted
__device__ float g_hpre[(size_t)T_MAX * WIDTH];     // one-hot part of layer0, per timestep

__global__ void init_kernel() {
    int i = blockIdx.x * blockDim.x + threadIdx.x;
    if (i < WIDTH) { g_h1p[i] = 0ull; g_h2p[i] = 0ull; }
    if (i < 2 * GRIDP * PPAD) g_pp[i] = 0ull;
    if (i < GRID) g_flags0[i] = 0;
    if (i == 0)   g_abort = 0;
}

// ------------------------------- helpers ----------------------------------
__device__ __forceinline__ void st_pair(u64* p, float v, unsigned e) {
    u64 x = ((u64)e << 32) | (u64)__float_as_uint(v);
    asm volatile("st.relaxed.gpu.global.u64 [%0], %1;" :: "l"(p), "l"(x) : "memory");
}
__device__ __forceinline__ int ld_abort() {
    int a;
    asm volatile("ld.global.cg.u32 %0, [%1];" : "=r"(a) : "l"(&g_abort) : "memory");
    return a;
}
__device__ __forceinline__ void set_abort() {
    asm volatile("st.global.cg.u32 [%0], %1;" :: "l"(&g_abort), "r"(1) : "memory");
}

// Per-thread: poll 2 consecutive pairs (one 16B load) until both epochs >= need.
// R12-verbatim cadence: nanosleep(100) every failed iteration.
__device__ __forceinline__ float2 poll2(const u64* base, unsigned need, int& dead) {
    if (dead) return make_float2(0.f, 0.f);
    unsigned cnt = 0;
    for (;;) {
        u64 a, b;
        asm volatile("ld.global.cg.v2.u64 {%0,%1}, [%2];"
                     : "=l"(a), "=l"(b) : "l"(base) : "memory");
        if ((unsigned)(a >> 32) >= need && (unsigned)(b >> 32) >= need)
            return make_float2(__uint_as_float((unsigned)a), __uint_as_float((unsigned)b));
        if ((++cnt & 63u) == 0u) {
            if (ld_abort()) { dead = 1; break; }
            if (cnt > POLL_BUDGET) { set_abort(); dead = 1; break; }
        }
        __nanosleep(100);
    }
    return make_float2(0.f, 0.f);
}

// Warp-collective: lane i polls padded partial slot i (own 128B line) until its
// epoch >= need; returns warp-sum of the 32 values. Bounded; zeros after abort.
__device__ __forceinline__ float poll_parts_warp(const u64* base, unsigned need,
                                                 int lane, int& dead) {
    if (dead) return 0.0f;
    const u64* p = base + (size_t)lane * PPAD;
    unsigned cnt = 0;
    u64 a;
    for (;;) {
        asm volatile("ld.global.cg.u64 %0, [%1];" : "=l"(a) : "l"(p) : "memory");
        bool ok = (unsigned)(a >> 32) >= need;
        if (__all_sync(0xffffffffu, ok)) break;
        if ((++cnt & 63u) == 0u) {
            if (ld_abort()) { dead = 1; a = 0; break; }
            if (cnt > POLL_BUDGET) { set_abort(); dead = 1; a = 0; break; }
        }
        __nanosleep(100);
    }
    float s = dead ? 0.0f : __uint_as_float((unsigned)a);
    #pragma unroll
    for (int d = 16; d > 0; d >>= 1) s += __shfl_xor_sync(0xffffffffu, s, d);
    return s;
}

// Bounded flag wait for the one-time precompute barrier (96 flags = 24 int4).
__device__ __forceinline__ void flagwait0(int lane) {
    int idx = (lane < 24) ? lane : (lane - 24);
    const int4* fp = reinterpret_cast<const int4*>(g_flags0) + idx;
    unsigned cnt = 0;
    for (;;) {
        int4 v; int ab;
        asm volatile("ld.global.cg.v4.u32 {%0,%1,%2,%3}, [%4];"
                     : "=r"(v.x), "=r"(v.y), "=r"(v.z), "=r"(v.w)
                     : "l"(fp) : "memory");
        asm volatile("ld.global.cg.u32 %0, [%1];"
                     : "=r"(ab) : "l"(&g_abort) : "memory");
        bool done = (v.x >= 1 && v.y >= 1 && v.z >= 1 && v.w >= 1) || (ab != 0);
        if (__all_sync(0xffffffffu, done)) break;
        if (++cnt > POLL_BUDGET) {
            if (lane == 0) set_abort();
            break;
        }
        __nanosleep(150);
    }
    __threadfence();
}

// One warp computes one dot(w_row[1024], h[1024]) from shared memory. (R12 verbatim)
__device__ __forceinline__ float gemv_warp(const float* __restrict__ wrow,
                                           const float* __restrict__ hbuf, int lane) {
    const float4* w4 = reinterpret_cast<const float4*>(wrow);
    const float4* h4 = reinterpret_cast<const float4*>(hbuf);
    float acc = 0.0f;
    #pragma unroll
    for (int i = 0; i < 8; i++) {
        float4 a = w4[i * 32 + lane];
        float4 b = h4[i * 32 + lane];
        acc += a.x * b.x + a.y * b.y + a.z * b.z + a.w * b.w;
    }
    #pragma unroll
    for (int d = 16; d > 0; d >>= 1) acc += __shfl_xor_sync(0xffffffffu, acc, d);
    return acc;
}

__global__ void __launch_bounds__(THREADS, 1)
seqff_kernel(const int* __restrict__ x,
             const float* __restrict__ W0,
             const float* __restrict__ b0,
             const float* __restrict__ Wh,
             const float* __restrict__ bh,
             const float* __restrict__ Wo,
             const float* __restrict__ bo,
             float* __restrict__ out,
             int T)
{
    extern __shared__ float smem[];
    float* Whs   = smem;                       // [32][1024] ONE layer's rows (128KB)
    float* hbuf  = Whs + CHUNK * WIDTH;        // 1024: staged input vector / h0
    float* ring  = hbuf + WIDTH;               // 16: y history window (group 0 only)
    float* wos   = ring + 16;                  // 32 (group 2 only)
    float* out32 = wos + 32;                   // 32: per-layer chunk outputs

    const int tid   = threadIdx.x;
    const int lane  = tid & 31;
    const int w     = tid >> 5;
    const int bid   = blockIdx.x;
    const int group = bid / GRIDP;             // 0: h0+L1, 1: L2, 2: L3+partial
    const int gid   = bid - group * GRIDP;
    const int o0    = gid * CHUNK;

    // ===================== load weights (once) =====================
    float2 wys[WS];
    #pragma unroll
    for (int k = 0; k < WS; k++)
        wys[k] = *reinterpret_cast<const float2*>(W0 + (size_t)(357 + k) * WIDTH + 2 * tid);

    for (int idx = tid; idx < CHUNK * WIDTH; idx += THREADS) {
        int r = idx >> 10, j = idx & (WIDTH - 1);
        Whs[idx] = Wh[(size_t)group * WIDTH * WIDTH + (size_t)j * WIDTH + o0 + r];
    }
    if (tid < CHUNK) wos[tid] = Wo[o0 + tid];
    if (tid < 16)    ring[tid] = -10.0f;
    const float bo_reg = __ldg(bo);
    const float bhA = __ldg(bh + (size_t)group * WIDTH + o0 + w);
    const float bhB = __ldg(bh + (size_t)group * WIDTH + o0 + w + 16);
    __syncthreads();

    // =============== precompute one-hot part of layer 0 for all t ===============
    for (int t = bid; t < T; t += GRID) {
        float2 acc = *reinterpret_cast<const float2*>(b0 + 2 * tid);
        if (t >= WS) {
            #pragma unroll
            for (int p = 0; p < WS + 1; p++) {
                int r = p * ALPHA + __ldg(x + t - WS + p);
                float2 wv = *reinterpret_cast<const float2*>(W0 + (size_t)r * WIDTH + 2 * tid);
                acc.x += wv.x; acc.y += wv.y;
            }
        } else {
            for (int p = 0; p < WS + 1; p++) {
                int pos = t - WS + p;
                if (pos >= 0) {
                    int r = p * ALPHA + __ldg(x + pos);
                    float2 wv = *reinterpret_cast<const float2*>(W0 + (size_t)r * WIDTH + 2 * tid);
                    acc.x += wv.x; acc.y += wv.y;
                } else {
                    for (int a = 0; a < ALPHA; a++) {
                        int r = p * ALPHA + a;
                        float2 wv = *reinterpret_cast<const float2*>(W0 + (size_t)r * WIDTH + 2 * tid);
                        acc.x += wv.x; acc.y += wv.y;
                    }
                }
            }
        }
        *reinterpret_cast<float2*>(g_hpre + (size_t)t * WIDTH + 2 * tid) = acc;
    }
    __syncthreads();
    if (tid == 0) {
        __threadfence();
        asm volatile("st.global.cg.u32 [%0], %1;" :: "l"(g_flags0 + bid), "r"(1) : "memory");
    }
    if (w == 0) flagwait0(lane);
    __syncthreads();

    float2 hpre_reg = make_float2(0.f, 0.f);
    if (group == 0)
        hpre_reg = *reinterpret_cast<const float2*>(g_hpre + 2 * tid);

    int dead = 0;

    // ============================ sequential main loop ============================
    for (int t = 0; t < T; t++) {
        if (group == 0) {
            // ---- y_{t-1}: WARP 0 ONLY polls 32 padded partial lines, broadcast via ring ----
            if (t > 0) {
                if (w == 0) {
                    float s = poll_parts_warp(g_pp + ((t - 1) & 1) * GRIDP * PPAD,
                                              (unsigned)t, lane, dead);
                    float y = fmaxf(s + bo_reg, 0.0f);
                    if (bid == 0 && lane == 0) out[t - 1] = y;
                    if (lane == 0) ring[(t + 15) & 15] = y;
                }
                __syncthreads();   // broadcast y (ring) to all warps
            }
            // full h0 locally (wys in registers, hpre prefetched)
            {
                float2 h = hpre_reg;
                #pragma unroll
                for (int k = 0; k < WS; k++) {
                    float yk = ring[(t + k) & 15];
                    h.x += yk * wys[k].x; h.y += yk * wys[k].y;
                }
                h.x = fmaxf(h.x, 0.0f); h.y = fmaxf(h.y, 0.0f);
                *reinterpret_cast<float2*>(hbuf + 2 * tid) = h;
            }
            __syncthreads();
            // layer-1 GEMV (2 rows/warp), coalesced publish h1 pairs
            {
                float v0 = gemv_warp(Whs + w * WIDTH, hbuf, lane);
                float v1 = gemv_warp(Whs + (w + 16) * WIDTH, hbuf, lane);
                if (lane == 0) {
                    out32[w]      = fmaxf(v0 + bhA, 0.0f);
                    out32[w + 16] = fmaxf(v1 + bhB, 0.0f);
                }
            }
            __syncthreads();
            if (tid < CHUNK)
                st_pair(&g_h1p[o0 + tid], out32[tid], (unsigned)(t + 1));
            // prefetch next step's hpre row
            if (t + 1 < T)
                hpre_reg = *reinterpret_cast<const float2*>(g_hpre + (size_t)(t + 1) * WIDTH + 2 * tid);
        } else if (group == 1) {
            // ---- poll full h1 (this thread's 2 dims), GEMV layer 2, publish h2 ----
            {
                float2 hv = poll2(g_h1p + 2 * tid, (unsigned)(t + 1), dead);
                *reinterpret_cast<float2*>(hbuf + 2 * tid) = hv;
            }
            __syncthreads();
            {
                float v0 = gemv_warp(Whs + w * WIDTH, hbuf, lane);
                float v1 = gemv_warp(Whs + (w + 16) * WIDTH, hbuf, lane);
                if (lane == 0) {
                    out32[w]      = fmaxf(v0 + bhA, 0.0f);
                    out32[w + 16] = fmaxf(v1 + bhB, 0.0f);
                }
            }
            __syncthreads();
            if (tid < CHUNK)
                st_pair(&g_h2p[o0 + tid], out32[tid], (unsigned)(t + 1));
            __syncthreads();   // protect hbuf WAR across iterations
        } else {
            // ---- poll full h2, GEMV layer 3, fold Wo dot, publish PADDED partial ----
            {
                float2 hv = poll2(g_h2p + 2 * tid, (unsigned)(t + 1), dead);
                *reinterpret_cast<float2*>(hbuf + 2 * tid) = hv;
            }
            __syncthreads();
            {
                float v0 = gemv_warp(Whs + w * WIDTH, hbuf, lane);
                float v1 = gemv_warp(Whs + (w + 16) * WIDTH, hbuf, lane);
                if (lane == 0) {
                    out32[w]      = fmaxf(v0 + bhA, 0.0f);
                    out32[w + 16] = fmaxf(v1 + bhB, 0.0f);
                }
            }
            __syncthreads();
            if (tid == 0) {
                float p = 0.0f;
                #pragma unroll
                for (int i = 0; i < CHUNK; i++) p += out32[i] * wos[i];
                st_pair(&g_pp[((t & 1) * GRIDP + gid) * PPAD], p, (unsigned)(t + 1));
            }
            __syncthreads();   // protect hbuf WAR across iterations
        }
    }

    // ---------------- epilogue: final output y[T-1] ----------------
    if (bid == 0 && w == 0) {
        float s = poll_parts_warp(g_pp + ((T - 1) & 1) * GRIDP * PPAD, (unsigned)T, lane, dead);
        if (lane == 0) out[T - 1] = fmaxf(s + bo_reg, 0.0f);
    }
}

extern "C" void kernel_launch(void* const* d_in, const int* in_sizes, int n_in,
                              void* d_out, int out_size)
{
    const int*   x  = (const int*)  d_in[0];
    const float* W0 = (const float*)d_in[1];
    const float* b0 = (const float*)d_in[2];
    const float* Wh = (const float*)d_in[3];
    const float* bh = (const float*)d_in[4];
    const float* Wo = (const float*)d_in[5];
    const float* bo = (const float*)d_in[6];
    float* out = (float*)d_out;
    int T = in_sizes[0];
    if (T > T_MAX) T = T_MAX;

    const int smem_bytes = (CHUNK * WIDTH + WIDTH + 16 + 32 + 32) * 4;  // ~136KB
    cudaFuncSetAttribute(seqff_kernel, cudaFuncAttributeMaxDynamicSharedMemorySize, smem_bytes);

    init_kernel<<<4, 512>>>();
    seqff_kernel<<<GRID, THREADS, smem_bytes>>>(x, W0, b0, Wh, bh, Wo, bo, out, T);
}